// round 11
// baseline (speedup 1.0000x reference)
#include <cuda_runtime.h>
#include <cuda_bf16.h>
#include <cstdint>

// Integration_4123168604342
// x: (T=128, B=4, E=10000, F=16) f32, dummy_index: int scalar
// out: (128, 4, 10000, 15) f32 = tanh(cumsum_T(f * dt))
//
// R11: persistent grid-stride variant of the plateau-best pipeline
// (scalar 16-lane-group mapping, depth-16 rotating buffers, __ldcs/__stcs).
// grid = 148 SMs x 6 resident blocks = 888; each block loops over 16-group
// tiles. One wave: no wave-transition cost, self-balancing tail. The memory
// side is at the mixed read/write HBM ceiling (~6 TB/s combined), proven
// invariant across R4/R5/R8/R10 — this round harvests scheduling overhead.

#define T_DIM   128
#define B_DIM   4
#define E_DIM   10000
#define F_DIM   16
#define FO_DIM  15
#define DEPTH   16
#define BE_DIM  (B_DIM * E_DIM)               // 40000 groups
#define STRIDE_T   ((size_t)BE_DIM * F_DIM)   // 640000 floats per t (input)
#define STRIDE_TO  ((size_t)BE_DIM * FO_DIM)  // 600000 floats per t (output)

#define GROUPS_PER_BLOCK 16                   // 256 threads / 16 lanes
#define NUM_TILES (BE_DIM / GROUPS_PER_BLOCK) // 2500
#define PERSISTENT_GRID (148 * 6)             // 888 resident blocks

__device__ __forceinline__ float tanh_fast(float x) {
    float y;
    asm("tanh.approx.f32 %0, %1;" : "=f"(y) : "f"(x));
    return y;
}

__global__ __launch_bounds__(256)
void integration_kernel(const float* __restrict__ x,
                        const int* __restrict__ didx,
                        float* __restrict__ out) {
    const int lane = threadIdx.x & 15;            // channel
    const int gsub = threadIdx.x >> 4;            // group slot within block

    const int d = *didx;                          // dummy (time) channel
    const bool is_t = (lane == d);
    const int oc = lane - (lane > d ? 1 : 0);     // output channel

    for (int tile = blockIdx.x; tile < NUM_TILES; tile += PERSISTENT_GRID) {
        const int group = tile * GROUPS_PER_BLOCK + gsub;

        const float* __restrict__ xp = x + (size_t)group * F_DIM + lane;
        float* __restrict__ op = out + (size_t)group * FO_DIM + oc;

        // ---- prologue: rows 0..15 in flight ----
        float b0  = __ldcs(xp);
        float b1  = __ldcs(xp + STRIDE_T);
        float b2  = __ldcs(xp + 2 * STRIDE_T);
        float b3  = __ldcs(xp + 3 * STRIDE_T);
        float b4  = __ldcs(xp + 4 * STRIDE_T);
        float b5  = __ldcs(xp + 5 * STRIDE_T);
        float b6  = __ldcs(xp + 6 * STRIDE_T);
        float b7  = __ldcs(xp + 7 * STRIDE_T);
        float b8  = __ldcs(xp + 8 * STRIDE_T);
        float b9  = __ldcs(xp + 9 * STRIDE_T);
        float b10 = __ldcs(xp + 10 * STRIDE_T);
        float b11 = __ldcs(xp + 11 * STRIDE_T);
        float b12 = __ldcs(xp + 12 * STRIDE_T);
        float b13 = __ldcs(xp + 13 * STRIDE_T);
        float b14 = __ldcs(xp + 14 * STRIDE_T);
        float b15 = __ldcs(xp + 15 * STRIDE_T);

        const float t0 = __shfl_sync(0xFFFFFFFFu, b0, d, 16);
        const float t1 = __shfl_sync(0xFFFFFFFFu, b1, d, 16);

        // t = 0: dt0 = t[0] + t[1]
        float acc = b0 * (t0 + t1);
        if (!is_t) __stcs(op, tanh_fast(acc));
        float prev_t = t0;

#define STEP(bv, k) do {                                                       \
        const float tc = __shfl_sync(0xFFFFFFFFu, (bv), d, 16);                \
        acc = fmaf((bv), tc - prev_t, acc);                                    \
        if (!is_t) __stcs(op + (size_t)(base + (k)) * STRIDE_TO,               \
                          tanh_fast(acc));                                     \
        prev_t = tc;                                                           \
        (bv) = __ldcs(xp + (size_t)(base + (k) + DEPTH) * STRIDE_T);           \
    } while (0)

#define STEP_NOLOAD(bv, k) do {                                                \
        const float tc = __shfl_sync(0xFFFFFFFFu, (bv), d, 16);                \
        acc = fmaf((bv), tc - prev_t, acc);                                    \
        if (!is_t) __stcs(op + (size_t)(base + (k)) * STRIDE_TO,               \
                          tanh_fast(acc));                                     \
        prev_t = tc;                                                           \
    } while (0)

        // ---- steady state: rows 0..111 consumed, rows 16..127 reloaded ----
        #pragma unroll 1
        for (int base = 0; base < T_DIM - DEPTH; base += DEPTH) {
            if (base > 0) STEP(b0, 0);
            else          b0 = __ldcs(xp + (size_t)DEPTH * STRIDE_T);
            STEP(b1,  1);
            STEP(b2,  2);
            STEP(b3,  3);
            STEP(b4,  4);
            STEP(b5,  5);
            STEP(b6,  6);
            STEP(b7,  7);
            STEP(b8,  8);
            STEP(b9,  9);
            STEP(b10, 10);
            STEP(b11, 11);
            STEP(b12, 12);
            STEP(b13, 13);
            STEP(b14, 14);
            STEP(b15, 15);
        }

        // ---- epilogue: rows 112..127 ----
        {
            const int base = T_DIM - DEPTH;
            STEP_NOLOAD(b0,  0);
            STEP_NOLOAD(b1,  1);
            STEP_NOLOAD(b2,  2);
            STEP_NOLOAD(b3,  3);
            STEP_NOLOAD(b4,  4);
            STEP_NOLOAD(b5,  5);
            STEP_NOLOAD(b6,  6);
            STEP_NOLOAD(b7,  7);
            STEP_NOLOAD(b8,  8);
            STEP_NOLOAD(b9,  9);
            STEP_NOLOAD(b10, 10);
            STEP_NOLOAD(b11, 11);
            STEP_NOLOAD(b12, 12);
            STEP_NOLOAD(b13, 13);
            STEP_NOLOAD(b14, 14);
            STEP_NOLOAD(b15, 15);
        }

#undef STEP
#undef STEP_NOLOAD
    }
}

extern "C" void kernel_launch(void* const* d_in, const int* in_sizes, int n_in,
                              void* d_out, int out_size) {
    const float* x   = (const float*)d_in[0];
    const int* didx  = (const int*)d_in[1];
    float* out       = (float*)d_out;

    integration_kernel<<<PERSISTENT_GRID, 256>>>(x, didx, out);
}

// round 12
// speedup vs baseline: 1.0056x; 1.0056x over previous
#include <cuda_runtime.h>
#include <cuda_bf16.h>
#include <cstdint>

// Integration_4123168604342
// x: (T=128, B=4, E=10000, F=16) f32, dummy_index: int scalar
// out: (128, 4, 10000, 15) f32 = tanh(cumsum_T(f * dt))
//
// R12: persistent single-wave grid (888 blocks) with CROSS-TILE software
// pipelining: the last 16-row block of tile i reloads rows 0..15 of the
// block's next tile, so the depth-16 rotating load pipeline never drains at
// tile boundaries (R11's regression). Otherwise identical to R8 (scalar
// 16-lane-group mapping, depth-16, __ldcs/__stcs).

#define T_DIM   128
#define B_DIM   4
#define E_DIM   10000
#define F_DIM   16
#define FO_DIM  15
#define DEPTH   16
#define BE_DIM  (B_DIM * E_DIM)               // 40000 groups
#define STRIDE_T   ((size_t)BE_DIM * F_DIM)   // 640000 floats per t (input)
#define STRIDE_TO  ((size_t)BE_DIM * FO_DIM)  // 600000 floats per t (output)

#define GROUPS_PER_BLOCK 16                   // 256 threads / 16 lanes
#define NUM_TILES (BE_DIM / GROUPS_PER_BLOCK) // 2500
#define PERSISTENT_GRID (148 * 6)             // 888 resident blocks (one wave)

__device__ __forceinline__ float tanh_fast(float x) {
    float y;
    asm("tanh.approx.f32 %0, %1;" : "=f"(y) : "f"(x));
    return y;
}

__global__ __launch_bounds__(256)
void integration_kernel(const float* __restrict__ x,
                        const int* __restrict__ didx,
                        float* __restrict__ out) {
    const int lane = threadIdx.x & 15;            // channel
    const int gsub = threadIdx.x >> 4;            // group slot within block

    const int d = *didx;                          // dummy (time) channel
    const bool is_t = (lane == d);
    const int oc = lane - (lane > d ? 1 : 0);     // output channel

    int tile = blockIdx.x;                        // 888 < 2500: always valid
    const float* __restrict__ xp =
        x + (size_t)(tile * GROUPS_PER_BLOCK + gsub) * F_DIM + lane;

    // ---- global prologue: rows 0..15 of first tile in flight ----
    float b0  = __ldcs(xp);
    float b1  = __ldcs(xp + STRIDE_T);
    float b2  = __ldcs(xp + 2 * STRIDE_T);
    float b3  = __ldcs(xp + 3 * STRIDE_T);
    float b4  = __ldcs(xp + 4 * STRIDE_T);
    float b5  = __ldcs(xp + 5 * STRIDE_T);
    float b6  = __ldcs(xp + 6 * STRIDE_T);
    float b7  = __ldcs(xp + 7 * STRIDE_T);
    float b8  = __ldcs(xp + 8 * STRIDE_T);
    float b9  = __ldcs(xp + 9 * STRIDE_T);
    float b10 = __ldcs(xp + 10 * STRIDE_T);
    float b11 = __ldcs(xp + 11 * STRIDE_T);
    float b12 = __ldcs(xp + 12 * STRIDE_T);
    float b13 = __ldcs(xp + 13 * STRIDE_T);
    float b14 = __ldcs(xp + 14 * STRIDE_T);
    float b15 = __ldcs(xp + 15 * STRIDE_T);

    while (true) {
        float* __restrict__ op =
            out + (size_t)(tile * GROUPS_PER_BLOCK + gsub) * FO_DIM + oc;

        const float t0 = __shfl_sync(0xFFFFFFFFu, b0, d, 16);
        const float t1 = __shfl_sync(0xFFFFFFFFu, b1, d, 16);

        // t = 0: dt0 = t[0] + t[1]
        float acc = b0 * (t0 + t1);
        if (!is_t) __stcs(op, tanh_fast(acc));
        float prev_t = t0;

        // consume row (base+k); reload slot from current tile row base+k+16
#define STEP(bv, k) do {                                                       \
        const float tc = __shfl_sync(0xFFFFFFFFu, (bv), d, 16);                \
        acc = fmaf((bv), tc - prev_t, acc);                                    \
        if (!is_t) __stcs(op + (size_t)(base + (k)) * STRIDE_TO,               \
                          tanh_fast(acc));                                     \
        prev_t = tc;                                                           \
        (bv) = __ldcs(xp + (size_t)(base + (k) + DEPTH) * STRIDE_T);           \
    } while (0)

        // consume row (112+k); reload slot from NEXT tile row k
#define STEP_X(bv, k) do {                                                     \
        const float tc = __shfl_sync(0xFFFFFFFFu, (bv), d, 16);                \
        acc = fmaf((bv), tc - prev_t, acc);                                    \
        if (!is_t) __stcs(op + (size_t)(112 + (k)) * STRIDE_TO,                \
                          tanh_fast(acc));                                     \
        prev_t = tc;                                                           \
        (bv) = __ldcs(xq + (size_t)(k) * STRIDE_T);                            \
    } while (0)

        // ---- rows 0..111 consumed; rows 16..127 of this tile reloaded ----
        #pragma unroll 1
        for (int base = 0; base < T_DIM - DEPTH; base += DEPTH) {
            if (base > 0) STEP(b0, 0);
            else          b0 = __ldcs(xp + (size_t)DEPTH * STRIDE_T);
            STEP(b1,  1);
            STEP(b2,  2);
            STEP(b3,  3);
            STEP(b4,  4);
            STEP(b5,  5);
            STEP(b6,  6);
            STEP(b7,  7);
            STEP(b8,  8);
            STEP(b9,  9);
            STEP(b10, 10);
            STEP(b11, 11);
            STEP(b12, 12);
            STEP(b13, 13);
            STEP(b14, 14);
            STEP(b15, 15);
        }

        // ---- rows 112..127 consumed; rows 0..15 of NEXT tile reloaded ----
        const int  next_tile = tile + PERSISTENT_GRID;
        const bool has_next  = next_tile < NUM_TILES;
        const float* __restrict__ xq = has_next
            ? x + (size_t)(next_tile * GROUPS_PER_BLOCK + gsub) * F_DIM + lane
            : xp;   // harmless hot re-reads on the final tile

        STEP_X(b0,  0);
        STEP_X(b1,  1);
        STEP_X(b2,  2);
        STEP_X(b3,  3);
        STEP_X(b4,  4);
        STEP_X(b5,  5);
        STEP_X(b6,  6);
        STEP_X(b7,  7);
        STEP_X(b8,  8);
        STEP_X(b9,  9);
        STEP_X(b10, 10);
        STEP_X(b11, 11);
        STEP_X(b12, 12);
        STEP_X(b13, 13);
        STEP_X(b14, 14);
        STEP_X(b15, 15);

#undef STEP
#undef STEP_X

        if (!has_next) break;
        tile = next_tile;
        xp = xq;
    }
}

extern "C" void kernel_launch(void* const* d_in, const int* in_sizes, int n_in,
                              void* d_out, int out_size) {
    const float* x   = (const float*)d_in[0];
    const int* didx  = (const int*)d_in[1];
    float* out       = (float*)d_out;

    integration_kernel<<<PERSISTENT_GRID, 256>>>(x, didx, out);
}

// round 13
// speedup vs baseline: 1.0756x; 1.0696x over previous
#include <cuda_runtime.h>
#include <cuda_bf16.h>
#include <cstdint>

// Integration_4123168604342
// x: (T=128, B=4, E=10000, F=16) f32, dummy_index: int scalar
// out: (128, 4, 10000, 15) f32 = tanh(cumsum_T(f * dt))
//
// R13 (final family): scalar 16-lane-group mapping, depth-16 rotating
// register pipeline, block 512 (32 groups: per-row output span = 1920B =
// 15 full L2 lines), streaming cache hints on both streams. This kernel
// family is at the mixed read/write HBM ceiling (~6 TB/s combined,
// DRAM ~70%), invariant across every structural axis tested in R4-R12.

#define T_DIM   128
#define B_DIM   4
#define E_DIM   10000
#define F_DIM   16
#define FO_DIM  15
#define DEPTH   16
#define BE_DIM  (B_DIM * E_DIM)               // 40000 groups
#define STRIDE_T   ((size_t)BE_DIM * F_DIM)   // 640000 floats per t (input)
#define STRIDE_TO  ((size_t)BE_DIM * FO_DIM)  // 600000 floats per t (output)

__device__ __forceinline__ float tanh_fast(float x) {
    float y;
    asm("tanh.approx.f32 %0, %1;" : "=f"(y) : "f"(x));
    return y;
}

__global__ __launch_bounds__(512)
void integration_kernel(const float* __restrict__ x,
                        const int* __restrict__ didx,
                        float* __restrict__ out) {
    const int gid   = blockIdx.x * blockDim.x + threadIdx.x;
    const int group = gid >> 4;       // (b,e) flat index
    const int lane  = gid & 15;       // channel

    const int d = *didx;              // dummy (time) channel
    const bool is_t = (lane == d);
    const int oc = lane - (lane > d ? 1 : 0);   // output channel for non-t lanes

    const float* __restrict__ xp = x + (size_t)group * F_DIM + lane;
    float* __restrict__ op = out + (size_t)group * FO_DIM + oc;

    // ---- prologue: rows 0..15 in flight ----
    float b0  = __ldcs(xp);
    float b1  = __ldcs(xp + STRIDE_T);
    float b2  = __ldcs(xp + 2 * STRIDE_T);
    float b3  = __ldcs(xp + 3 * STRIDE_T);
    float b4  = __ldcs(xp + 4 * STRIDE_T);
    float b5  = __ldcs(xp + 5 * STRIDE_T);
    float b6  = __ldcs(xp + 6 * STRIDE_T);
    float b7  = __ldcs(xp + 7 * STRIDE_T);
    float b8  = __ldcs(xp + 8 * STRIDE_T);
    float b9  = __ldcs(xp + 9 * STRIDE_T);
    float b10 = __ldcs(xp + 10 * STRIDE_T);
    float b11 = __ldcs(xp + 11 * STRIDE_T);
    float b12 = __ldcs(xp + 12 * STRIDE_T);
    float b13 = __ldcs(xp + 13 * STRIDE_T);
    float b14 = __ldcs(xp + 14 * STRIDE_T);
    float b15 = __ldcs(xp + 15 * STRIDE_T);

    const float t0 = __shfl_sync(0xFFFFFFFFu, b0, d, 16);
    const float t1 = __shfl_sync(0xFFFFFFFFu, b1, d, 16);

    // t = 0: dt0 = t[0] + t[1]
    float acc = b0 * (t0 + t1);
    if (!is_t) __stcs(op, tanh_fast(acc));
    float prev_t = t0;

    // consume buffer bv as row (base+k), then reload bv from row (base+k+DEPTH)
#define STEP(bv, k) do {                                                       \
        const float tc = __shfl_sync(0xFFFFFFFFu, (bv), d, 16);                \
        acc = fmaf((bv), tc - prev_t, acc);                                    \
        if (!is_t) __stcs(op + (size_t)(base + (k)) * STRIDE_TO,               \
                          tanh_fast(acc));                                     \
        prev_t = tc;                                                           \
        (bv) = __ldcs(xp + (size_t)(base + (k) + DEPTH) * STRIDE_T);           \
    } while (0)

#define STEP_NOLOAD(bv, k) do {                                                \
        const float tc = __shfl_sync(0xFFFFFFFFu, (bv), d, 16);                \
        acc = fmaf((bv), tc - prev_t, acc);                                    \
        if (!is_t) __stcs(op + (size_t)(base + (k)) * STRIDE_TO,               \
                          tanh_fast(acc));                                     \
        prev_t = tc;                                                           \
    } while (0)

    // ---- steady state: rows 0..111 consumed, rows 16..127 reloaded ----
    #pragma unroll 1
    for (int base = 0; base < T_DIM - DEPTH; base += DEPTH) {
        if (base > 0) STEP(b0, 0);
        else          b0 = __ldcs(xp + (size_t)DEPTH * STRIDE_T);  // row 0 done
        STEP(b1,  1);
        STEP(b2,  2);
        STEP(b3,  3);
        STEP(b4,  4);
        STEP(b5,  5);
        STEP(b6,  6);
        STEP(b7,  7);
        STEP(b8,  8);
        STEP(b9,  9);
        STEP(b10, 10);
        STEP(b11, 11);
        STEP(b12, 12);
        STEP(b13, 13);
        STEP(b14, 14);
        STEP(b15, 15);
    }

    // ---- epilogue: rows 112..127, no more loads ----
    {
        const int base = T_DIM - DEPTH;
        STEP_NOLOAD(b0,  0);
        STEP_NOLOAD(b1,  1);
        STEP_NOLOAD(b2,  2);
        STEP_NOLOAD(b3,  3);
        STEP_NOLOAD(b4,  4);
        STEP_NOLOAD(b5,  5);
        STEP_NOLOAD(b6,  6);
        STEP_NOLOAD(b7,  7);
        STEP_NOLOAD(b8,  8);
        STEP_NOLOAD(b9,  9);
        STEP_NOLOAD(b10, 10);
        STEP_NOLOAD(b11, 11);
        STEP_NOLOAD(b12, 12);
        STEP_NOLOAD(b13, 13);
        STEP_NOLOAD(b14, 14);
        STEP_NOLOAD(b15, 15);
    }

#undef STEP
#undef STEP_NOLOAD
}

extern "C" void kernel_launch(void* const* d_in, const int* in_sizes, int n_in,
                              void* d_out, int out_size) {
    const float* x   = (const float*)d_in[0];
    const int* didx  = (const int*)d_in[1];
    float* out       = (float*)d_out;

    const int total_threads = BE_DIM * 16;        // 640000
    const int block = 512;
    const int grid = total_threads / block;       // 1250 exact
    integration_kernel<<<grid, block>>>(x, didx, out);
}

// round 14
// speedup vs baseline: 1.1422x; 1.0620x over previous
#include <cuda_runtime.h>
#include <cuda_bf16.h>
#include <cstdint>

// Integration_4123168604342
// x: (T=128, B=4, E=10000, F=16) f32, dummy_index: int scalar
// out: (128, 4, 10000, 15) f32 = tanh(cumsum_T(f * dt))
//
// R14: bulk async write path. Block=512 covers 32 groups -> per-row output
// span = 1920 contiguous bytes (16B-aligned, 15 full 128B lines). Each 8-row
// chunk is computed into smem, then ONE thread issues 8 cp.async.bulk
// shared->global copies of 1920B (async proxy, full-line bursts). Double-
// buffered (2 x 8 x 1920B = 30KB), wait_group.read for reuse. Read side keeps
// the proven depth-16 rotating __ldcs pipeline. Row 0 folded into the uniform
// recurrence via prev_t = -t1 (dt0 = t0 + t1).

#define T_DIM   128
#define B_DIM   4
#define E_DIM   10000
#define F_DIM   16
#define FO_DIM  15
#define DEPTH   16
#define BE_DIM  (B_DIM * E_DIM)               // 40000 groups
#define STRIDE_T   ((size_t)BE_DIM * F_DIM)   // 640000 floats per t (input)
#define STRIDE_TO  ((size_t)BE_DIM * FO_DIM)  // 600000 floats per t (output)

#define GROUPS_PB   32                        // 512 threads / 16 lanes
#define ROW_FLOATS  (GROUPS_PB * FO_DIM)      // 480 floats = 1920 B per row
#define ROW_BYTES   (ROW_FLOATS * 4)          // 1920
#define CHUNK       8                         // rows per bulk-commit group

__device__ __forceinline__ float tanh_fast(float x) {
    float y;
    asm("tanh.approx.f32 %0, %1;" : "=f"(y) : "f"(x));
    return y;
}

__global__ __launch_bounds__(512)
void integration_kernel(const float* __restrict__ x,
                        const int* __restrict__ didx,
                        float* __restrict__ out) {
    __shared__ float sbuf[2][CHUNK][ROW_FLOATS];   // 30720 B

    const int tid  = threadIdx.x;
    const int gsub = tid >> 4;        // group slot within block (0..31)
    const int lane = tid & 15;        // channel
    const int group = blockIdx.x * GROUPS_PB + gsub;

    const int d = *didx;              // dummy (time) channel (uniform)
    const bool is_t = (lane == d);
    const int oc = lane - (lane > d ? 1 : 0);
    const int scol = gsub * FO_DIM + oc;          // smem column for this lane

    const float* __restrict__ xp = x + (size_t)group * F_DIM + lane;
    // block's output base: byte offset blockIdx.x*1920 (16B aligned)
    const float* out_blk = out + (size_t)blockIdx.x * ROW_FLOATS;

    uint32_t sbase;
    asm("{ .reg .u64 t; cvta.to.shared.u64 t, %1; cvt.u32.u64 %0, t; }"
        : "=r"(sbase) : "l"((const void*)&sbuf[0][0][0]));

    // ---- prologue: rows 0..15 in flight (depth-16 rotating pipeline) ----
    float b0  = __ldcs(xp);
    float b1  = __ldcs(xp + STRIDE_T);
    float b2  = __ldcs(xp + 2 * STRIDE_T);
    float b3  = __ldcs(xp + 3 * STRIDE_T);
    float b4  = __ldcs(xp + 4 * STRIDE_T);
    float b5  = __ldcs(xp + 5 * STRIDE_T);
    float b6  = __ldcs(xp + 6 * STRIDE_T);
    float b7  = __ldcs(xp + 7 * STRIDE_T);
    float b8  = __ldcs(xp + 8 * STRIDE_T);
    float b9  = __ldcs(xp + 9 * STRIDE_T);
    float b10 = __ldcs(xp + 10 * STRIDE_T);
    float b11 = __ldcs(xp + 11 * STRIDE_T);
    float b12 = __ldcs(xp + 12 * STRIDE_T);
    float b13 = __ldcs(xp + 13 * STRIDE_T);
    float b14 = __ldcs(xp + 14 * STRIDE_T);
    float b15 = __ldcs(xp + 15 * STRIDE_T);

    // Fold row-0 special case into the uniform recurrence:
    // row 0 computes dt = t0 - prev_t; want t0 + t1 => prev_t = -t1.
    const float t1 = __shfl_sync(0xFFFFFFFFu, b1, d, 16);
    float acc = 0.0f;
    float prev_t = -t1;

    // consume buffer bv as row (base+k) into smem row k, reload from base+k+16
#define STEP(bv, k, sb) do {                                                   \
        const float tc = __shfl_sync(0xFFFFFFFFu, (bv), d, 16);                \
        acc = fmaf((bv), tc - prev_t, acc);                                    \
        if (!is_t) (sb)[(k) * ROW_FLOATS + scol] = tanh_fast(acc);             \
        prev_t = tc;                                                           \
        const int r_ = base + (k) + DEPTH;                                     \
        if (r_ < T_DIM) (bv) = __ldcs(xp + (size_t)r_ * STRIDE_T);             \
    } while (0)

    #pragma unroll 1
    for (int chunk = 0; chunk < T_DIM / CHUNK; ++chunk) {
        const int base = chunk * CHUNK;
        const int buf  = chunk & 1;
        float* sb = &sbuf[buf][0][0];

        // release buffer `buf` (written 2 chunks ago): wait until its bulk
        // copies have finished READING smem, then barrier so all threads know.
        if (chunk >= 2 && tid == 0)
            asm volatile("cp.async.bulk.wait_group.read 1;" ::: "memory");
        __syncthreads();

        // ---- compute 8 rows into smem ----
        if (buf == 0) {
            STEP(b0, 0, sb); STEP(b1, 1, sb); STEP(b2, 2, sb); STEP(b3, 3, sb);
            STEP(b4, 4, sb); STEP(b5, 5, sb); STEP(b6, 6, sb); STEP(b7, 7, sb);
        } else {
            STEP(b8,  0, sb); STEP(b9,  1, sb); STEP(b10, 2, sb); STEP(b11, 3, sb);
            STEP(b12, 4, sb); STEP(b13, 5, sb); STEP(b14, 6, sb); STEP(b15, 7, sb);
        }
        __syncthreads();   // STS visible to issuing thread

        // ---- one thread issues 8 bulk copies (1920B each) + commit ----
        if (tid == 0) {
            asm volatile("fence.proxy.async.shared::cta;" ::: "memory");
            const uint32_t s0 = sbase + (uint32_t)(buf * CHUNK * ROW_BYTES);
            #pragma unroll
            for (int k = 0; k < CHUNK; ++k) {
                const float* g = out_blk + (size_t)(base + k) * STRIDE_TO;
                asm volatile(
                    "cp.async.bulk.global.shared::cta.bulk_group [%0], [%1], %2;"
                    :: "l"(g), "r"(s0 + (uint32_t)(k * ROW_BYTES)), "n"(ROW_BYTES)
                    : "memory");
            }
            asm volatile("cp.async.bulk.commit_group;" ::: "memory");
        }
    }

#undef STEP

    // ensure all bulk stores complete before kernel exit
    if (tid == 0)
        asm volatile("cp.async.bulk.wait_group 0;" ::: "memory");
}

extern "C" void kernel_launch(void* const* d_in, const int* in_sizes, int n_in,
                              void* d_out, int out_size) {
    const float* x   = (const float*)d_in[0];
    const int* didx  = (const int*)d_in[1];
    float* out       = (float*)d_out;

    const int grid = BE_DIM / GROUPS_PB;          // 1250 exact
    integration_kernel<<<grid, 512>>>(x, didx, out);
}

// round 15
// speedup vs baseline: 1.1864x; 1.0387x over previous
#include <cuda_runtime.h>
#include <cuda_bf16.h>
#include <cstdint>

// Integration_4123168604342
// x: (T=128, B=4, E=10000, F=16) f32, dummy_index: int scalar
// out: (128, 4, 10000, 15) f32 = tanh(cumsum_T(f * dt))
//
// R15: BOTH streams through the bulk async copy engines.
//   reads : cp.async.bulk.shared::cta.global + mbarrier, 8 x 2048B per chunk
//           (block's per-row input span is 2048 contiguous bytes), STAGES=4
//           pipeline (48KB of reads in flight per block).
//   writes: cp.async.bulk.global.shared::cta (R14's proven path), 8 x 1920B
//           per chunk, double-buffered, wait_group.read recycling.
// SM work is only LDS -> fma -> tanh -> STS; no LDG, no STG, no shfl
// (t-channel read directly from smem: conflict-free broadcast).

#define T_DIM   128
#define B_DIM   4
#define E_DIM   10000
#define F_DIM   16
#define FO_DIM  15
#define BE_DIM  (B_DIM * E_DIM)               // 40000 groups
#define STRIDE_T   ((size_t)BE_DIM * F_DIM)   // 640000 floats per t (input)
#define STRIDE_TO  ((size_t)BE_DIM * FO_DIM)  // 600000 floats per t (output)

#define GROUPS_PB      32
#define THREADS        512
#define IN_ROW_FLOATS  (GROUPS_PB * F_DIM)    // 512 floats = 2048 B
#define IN_ROW_BYTES   2048
#define OUT_ROW_FLOATS (GROUPS_PB * FO_DIM)   // 480 floats = 1920 B
#define OUT_ROW_BYTES  1920
#define CHUNK          8
#define NCHUNK         (T_DIM / CHUNK)        // 16
#define STAGES         4
#define IN_STAGE_BYTES  (CHUNK * IN_ROW_BYTES)     // 16384
#define SMEM_IN_BYTES   (STAGES * IN_STAGE_BYTES)  // 65536
#define SMEM_OUT_BYTES  (2 * CHUNK * OUT_ROW_BYTES)// 30720
#define SMEM_TOTAL      (SMEM_IN_BYTES + SMEM_OUT_BYTES)  // 96256

__device__ __forceinline__ float tanh_fast(float x) {
    float y;
    asm("tanh.approx.f32 %0, %1;" : "=f"(y) : "f"(x));
    return y;
}

__device__ __forceinline__ uint32_t smem_u32(const void* p) {
    uint32_t a;
    asm("{ .reg .u64 t; cvta.to.shared.u64 t, %1; cvt.u32.u64 %0, t; }"
        : "=r"(a) : "l"(p));
    return a;
}

__device__ __forceinline__ void mbar_wait_parity(uint32_t mb, uint32_t parity) {
    uint32_t done;
    asm volatile(
        "{\n\t.reg .pred p;\n\t"
        "mbarrier.try_wait.parity.acquire.cta.shared::cta.b64 p, [%1], %2;\n\t"
        "selp.b32 %0, 1, 0, p;\n\t}"
        : "=r"(done) : "r"(mb), "r"(parity) : "memory");
    if (!done) {
        asm volatile(
            "{\n\t.reg .pred P1;\n\t"
            "WAIT_LOOP_%=:\n\t"
            "mbarrier.try_wait.parity.acquire.cta.shared::cta.b64 P1, [%0], %1, 0x989680;\n\t"
            "@P1 bra.uni WAIT_DONE_%=;\n\t"
            "bra.uni WAIT_LOOP_%=;\n\t"
            "WAIT_DONE_%=:\n\t}"
            :: "r"(mb), "r"(parity) : "memory");
    }
}

__global__ __launch_bounds__(THREADS)
void integration_kernel(const float* __restrict__ x,
                        const int* __restrict__ didx,
                        float* __restrict__ out) {
    extern __shared__ char smem[];
    float* in_base  = (float*)smem;                          // [STAGES][CHUNK][512]
    float* out_base = (float*)(smem + SMEM_IN_BYTES);        // [2][CHUNK][480]
    __shared__ uint64_t mbar[STAGES];

    const uint32_t in_addr   = smem_u32(in_base);
    const uint32_t out_addr  = smem_u32(out_base);
    const uint32_t mbar_addr = smem_u32(&mbar[0]);

    const int tid  = threadIdx.x;
    const int gsub = tid >> 4;
    const int lane = tid & 15;

    const int d = *didx;                         // uniform time channel
    const bool is_t = (lane == d);
    const int oc = lane - (lane > d ? 1 : 0);
    const int scol  = gsub * FO_DIM + oc;        // out smem column
    const int tbase = gsub * F_DIM + d;          // in smem column of t-value

    // global byte bases for this block's row spans
    const char* gin  = (const char*)x + (size_t)blockIdx.x * IN_ROW_BYTES;
    const char* gout = (const char*)out + (size_t)blockIdx.x * OUT_ROW_BYTES;

    // ---- init mbarriers ----
    if (tid == 0) {
        #pragma unroll
        for (int s = 0; s < STAGES; ++s)
            asm volatile("mbarrier.init.shared.b64 [%0], %1;"
                         :: "r"(mbar_addr + s * 8), "r"(1) : "memory");
    }
    __syncthreads();

    // issue bulk loads for chunk c into stage s (tid 0 only)
#define ISSUE_LOAD(c_, s_) do {                                                \
        const uint32_t mb_ = mbar_addr + (s_) * 8;                             \
        asm volatile("mbarrier.arrive.expect_tx.shared.b64 _, [%0], %1;"       \
                     :: "r"(mb_), "r"((uint32_t)IN_STAGE_BYTES) : "memory");   \
        _Pragma("unroll")                                                      \
        for (int k_ = 0; k_ < CHUNK; ++k_) {                                   \
            const char* g_ = gin +                                             \
                (size_t)((c_) * CHUNK + k_) * (STRIDE_T * 4);                  \
            const uint32_t ds_ = in_addr + (s_) * IN_STAGE_BYTES               \
                                 + k_ * IN_ROW_BYTES;                          \
            asm volatile(                                                      \
                "cp.async.bulk.shared::cta.global.mbarrier::complete_tx::bytes"\
                " [%0], [%1], %2, [%3];"                                       \
                :: "r"(ds_), "l"(g_), "r"((uint32_t)IN_ROW_BYTES), "r"(mb_)    \
                : "memory");                                                   \
        }                                                                      \
    } while (0)

    // ---- prologue: fill all STAGES ----
    if (tid == 0) {
        #pragma unroll
        for (int s = 0; s < STAGES; ++s) ISSUE_LOAD(s, s);
    }

    float acc = 0.0f;
    float prev_t = 0.0f;

    #pragma unroll 1
    for (int c = 0; c < NCHUNK; ++c) {
        const int s  = c & (STAGES - 1);
        const int ph = (c / STAGES) & 1;
        const uint32_t mb = mbar_addr + s * 8;

        // ---- wait input chunk ready (acquire) ----
        mbar_wait_parity(mb, (uint32_t)ph);

        const float* ib = in_base + (size_t)s * (CHUNK * IN_ROW_FLOATS);

        // fold row-0 special case: dt0 = t0 + t1  =>  prev_t = -t1
        if (c == 0) prev_t = -ib[IN_ROW_FLOATS + tbase];

        // ---- compute 8 rows into registers ----
        float r[CHUNK];
        #pragma unroll
        for (int k = 0; k < CHUNK; ++k) {
            const float v  = ib[k * IN_ROW_FLOATS + tid];
            const float tc = ib[k * IN_ROW_FLOATS + tbase];
            acc = fmaf(v, tc - prev_t, acc);
            r[k] = tanh_fast(acc);
            prev_t = tc;
        }

        // ---- recycle output buffer written 2 chunks ago ----
        if (tid == 0 && c >= 2)
            asm volatile("cp.async.bulk.wait_group.read 1;" ::: "memory");
        __syncthreads();   // all reads of stage s done + out_buf[c&1] free

        // ---- refill this input stage for chunk c+STAGES ----
        if (tid == 0 && c + STAGES < NCHUNK) ISSUE_LOAD(c + STAGES, s);

        // ---- stage results to smem ----
        float* ob = out_base + (size_t)(c & 1) * (CHUNK * OUT_ROW_FLOATS);
        if (!is_t) {
            #pragma unroll
            for (int k = 0; k < CHUNK; ++k)
                ob[k * OUT_ROW_FLOATS + scol] = r[k];
        }
        __syncthreads();   // STS visible to issuing thread

        // ---- issue 8 bulk stores (1920B each) + commit ----
        if (tid == 0) {
            asm volatile("fence.proxy.async.shared::cta;" ::: "memory");
            const uint32_t s0 = out_addr + (uint32_t)((c & 1) * CHUNK * OUT_ROW_BYTES);
            #pragma unroll
            for (int k = 0; k < CHUNK; ++k) {
                const char* g = gout + (size_t)(c * CHUNK + k) * (STRIDE_TO * 4);
                asm volatile(
                    "cp.async.bulk.global.shared::cta.bulk_group [%0], [%1], %2;"
                    :: "l"(g), "r"(s0 + (uint32_t)(k * OUT_ROW_BYTES)),
                       "r"((uint32_t)OUT_ROW_BYTES)
                    : "memory");
            }
            asm volatile("cp.async.bulk.commit_group;" ::: "memory");
        }
    }

#undef ISSUE_LOAD

    // drain outstanding stores before exit
    if (tid == 0)
        asm volatile("cp.async.bulk.wait_group 0;" ::: "memory");
}

extern "C" void kernel_launch(void* const* d_in, const int* in_sizes, int n_in,
                              void* d_out, int out_size) {
    const float* x   = (const float*)d_in[0];
    const int* didx  = (const int*)d_in[1];
    float* out       = (float*)d_out;

    cudaFuncSetAttribute(integration_kernel,
                         cudaFuncAttributeMaxDynamicSharedMemorySize, SMEM_TOTAL);
    const int grid = BE_DIM / GROUPS_PB;          // 1250 exact
    integration_kernel<<<grid, THREADS, SMEM_TOTAL>>>(x, didx, out);
}

// round 16
// speedup vs baseline: 1.1929x; 1.0054x over previous
#include <cuda_runtime.h>
#include <cuda_bf16.h>
#include <cstdint>

// Integration_4123168604342
// x: (T=128, B=4, E=10000, F=16) f32, dummy_index: int scalar
// out: (128, 4, 10000, 15) f32 = tanh(cumsum_T(f * dt))
//
// R16: R15 (dual bulk-async streams: cp.async.bulk G2S reads with mbarrier,
// cp.async.bulk S2G writes with bulk_group) with:
//   - STAGES 4 -> 2: smem 96KB -> 62.5KB -> 3 blocks/SM (was 2). Aggregate
//     read prefetch unchanged (~96KB/SM) but 3 independent chunk pipelines
//     per SM smooth DRAM demand and hide each block's serialized tid0 work.
//   - wait_group.read hoisted to chunk start (off the critical path).

#define T_DIM   128
#define B_DIM   4
#define E_DIM   10000
#define F_DIM   16
#define FO_DIM  15
#define BE_DIM  (B_DIM * E_DIM)               // 40000 groups
#define STRIDE_T   ((size_t)BE_DIM * F_DIM)   // 640000 floats per t (input)
#define STRIDE_TO  ((size_t)BE_DIM * FO_DIM)  // 600000 floats per t (output)

#define GROUPS_PB      32
#define THREADS        512
#define IN_ROW_FLOATS  (GROUPS_PB * F_DIM)    // 512 floats = 2048 B
#define IN_ROW_BYTES   2048
#define OUT_ROW_FLOATS (GROUPS_PB * FO_DIM)   // 480 floats = 1920 B
#define OUT_ROW_BYTES  1920
#define CHUNK          8
#define NCHUNK         (T_DIM / CHUNK)        // 16
#define STAGES         2
#define IN_STAGE_BYTES  (CHUNK * IN_ROW_BYTES)     // 16384
#define SMEM_IN_BYTES   (STAGES * IN_STAGE_BYTES)  // 32768
#define SMEM_OUT_BYTES  (2 * CHUNK * OUT_ROW_BYTES)// 30720
#define SMEM_TOTAL      (SMEM_IN_BYTES + SMEM_OUT_BYTES)  // 63488

__device__ __forceinline__ float tanh_fast(float x) {
    float y;
    asm("tanh.approx.f32 %0, %1;" : "=f"(y) : "f"(x));
    return y;
}

__device__ __forceinline__ uint32_t smem_u32(const void* p) {
    uint32_t a;
    asm("{ .reg .u64 t; cvta.to.shared.u64 t, %1; cvt.u32.u64 %0, t; }"
        : "=r"(a) : "l"(p));
    return a;
}

__device__ __forceinline__ void mbar_wait_parity(uint32_t mb, uint32_t parity) {
    uint32_t done;
    asm volatile(
        "{\n\t.reg .pred p;\n\t"
        "mbarrier.try_wait.parity.acquire.cta.shared::cta.b64 p, [%1], %2;\n\t"
        "selp.b32 %0, 1, 0, p;\n\t}"
        : "=r"(done) : "r"(mb), "r"(parity) : "memory");
    if (!done) {
        asm volatile(
            "{\n\t.reg .pred P1;\n\t"
            "WAIT_LOOP_%=:\n\t"
            "mbarrier.try_wait.parity.acquire.cta.shared::cta.b64 P1, [%0], %1, 0x989680;\n\t"
            "@P1 bra.uni WAIT_DONE_%=;\n\t"
            "bra.uni WAIT_LOOP_%=;\n\t"
            "WAIT_DONE_%=:\n\t}"
            :: "r"(mb), "r"(parity) : "memory");
    }
}

__global__ __launch_bounds__(THREADS)
void integration_kernel(const float* __restrict__ x,
                        const int* __restrict__ didx,
                        float* __restrict__ out) {
    extern __shared__ char smem[];
    float* in_base  = (float*)smem;                          // [STAGES][CHUNK][512]
    float* out_base = (float*)(smem + SMEM_IN_BYTES);        // [2][CHUNK][480]
    __shared__ uint64_t mbar[STAGES];

    const uint32_t in_addr   = smem_u32(in_base);
    const uint32_t out_addr  = smem_u32(out_base);
    const uint32_t mbar_addr = smem_u32(&mbar[0]);

    const int tid  = threadIdx.x;
    const int gsub = tid >> 4;
    const int lane = tid & 15;

    const int d = *didx;                         // uniform time channel
    const bool is_t = (lane == d);
    const int oc = lane - (lane > d ? 1 : 0);
    const int scol  = gsub * FO_DIM + oc;        // out smem column
    const int tbase = gsub * F_DIM + d;          // in smem column of t-value

    // global byte bases for this block's row spans
    const char* gin  = (const char*)x + (size_t)blockIdx.x * IN_ROW_BYTES;
    const char* gout = (const char*)out + (size_t)blockIdx.x * OUT_ROW_BYTES;

    // ---- init mbarriers ----
    if (tid == 0) {
        #pragma unroll
        for (int s = 0; s < STAGES; ++s)
            asm volatile("mbarrier.init.shared.b64 [%0], %1;"
                         :: "r"(mbar_addr + s * 8), "r"(1) : "memory");
    }
    __syncthreads();

    // issue bulk loads for chunk c into stage s (tid 0 only)
#define ISSUE_LOAD(c_, s_) do {                                                \
        const uint32_t mb_ = mbar_addr + (s_) * 8;                             \
        asm volatile("mbarrier.arrive.expect_tx.shared.b64 _, [%0], %1;"       \
                     :: "r"(mb_), "r"((uint32_t)IN_STAGE_BYTES) : "memory");   \
        _Pragma("unroll")                                                      \
        for (int k_ = 0; k_ < CHUNK; ++k_) {                                   \
            const char* g_ = gin +                                             \
                (size_t)((c_) * CHUNK + k_) * (STRIDE_T * 4);                  \
            const uint32_t ds_ = in_addr + (s_) * IN_STAGE_BYTES               \
                                 + k_ * IN_ROW_BYTES;                          \
            asm volatile(                                                      \
                "cp.async.bulk.shared::cta.global.mbarrier::complete_tx::bytes"\
                " [%0], [%1], %2, [%3];"                                       \
                :: "r"(ds_), "l"(g_), "r"((uint32_t)IN_ROW_BYTES), "r"(mb_)    \
                : "memory");                                                   \
        }                                                                      \
    } while (0)

    // ---- prologue: fill both stages ----
    if (tid == 0) {
        #pragma unroll
        for (int s = 0; s < STAGES; ++s) ISSUE_LOAD(s, s);
    }

    float acc = 0.0f;
    float prev_t = 0.0f;

    #pragma unroll 1
    for (int c = 0; c < NCHUNK; ++c) {
        const int s  = c & (STAGES - 1);
        const int ph = (c / STAGES) & 1;
        const uint32_t mb = mbar_addr + s * 8;

        // recycle the output buffer written 2 chunks ago (early: off the
        // critical path — those stores have long drained by now). Only
        // constraint is that this precedes the STS below (it does, via the
        // barrier between).
        if (tid == 0 && c >= 2)
            asm volatile("cp.async.bulk.wait_group.read 1;" ::: "memory");

        // ---- wait input chunk ready (acquire) ----
        mbar_wait_parity(mb, (uint32_t)ph);

        const float* ib = in_base + (size_t)s * (CHUNK * IN_ROW_FLOATS);

        // fold row-0 special case: dt0 = t0 + t1  =>  prev_t = -t1
        if (c == 0) prev_t = -ib[IN_ROW_FLOATS + tbase];

        // ---- compute 8 rows into registers ----
        float r[CHUNK];
        #pragma unroll
        for (int k = 0; k < CHUNK; ++k) {
            const float v  = ib[k * IN_ROW_FLOATS + tid];
            const float tc = ib[k * IN_ROW_FLOATS + tbase];
            acc = fmaf(v, tc - prev_t, acc);
            r[k] = tanh_fast(acc);
            prev_t = tc;
        }

        __syncthreads();   // stage-s reads done by all; tid0's wait done

        // ---- refill this input stage for chunk c+STAGES ----
        if (tid == 0 && c + STAGES < NCHUNK) ISSUE_LOAD(c + STAGES, s);

        // ---- stage results to smem ----
        float* ob = out_base + (size_t)(c & 1) * (CHUNK * OUT_ROW_FLOATS);
        if (!is_t) {
            #pragma unroll
            for (int k = 0; k < CHUNK; ++k)
                ob[k * OUT_ROW_FLOATS + scol] = r[k];
        }
        __syncthreads();   // STS visible to issuing thread

        // ---- issue 8 bulk stores (1920B each) + commit ----
        if (tid == 0) {
            asm volatile("fence.proxy.async.shared::cta;" ::: "memory");
            const uint32_t s0 = out_addr + (uint32_t)((c & 1) * CHUNK * OUT_ROW_BYTES);
            #pragma unroll
            for (int k = 0; k < CHUNK; ++k) {
                const char* g = gout + (size_t)(c * CHUNK + k) * (STRIDE_TO * 4);
                asm volatile(
                    "cp.async.bulk.global.shared::cta.bulk_group [%0], [%1], %2;"
                    :: "l"(g), "r"(s0 + (uint32_t)(k * OUT_ROW_BYTES)),
                       "r"((uint32_t)OUT_ROW_BYTES)
                    : "memory");
            }
            asm volatile("cp.async.bulk.commit_group;" ::: "memory");
        }
    }

#undef ISSUE_LOAD

    // drain outstanding stores before exit
    if (tid == 0)
        asm volatile("cp.async.bulk.wait_group 0;" ::: "memory");
}

extern "C" void kernel_launch(void* const* d_in, const int* in_sizes, int n_in,
                              void* d_out, int out_size) {
    const float* x   = (const float*)d_in[0];
    const int* didx  = (const int*)d_in[1];
    float* out       = (float*)d_out;

    cudaFuncSetAttribute(integration_kernel,
                         cudaFuncAttributeMaxDynamicSharedMemorySize, SMEM_TOTAL);
    const int grid = BE_DIM / GROUPS_PB;          // 1250 exact
    integration_kernel<<<grid, THREADS, SMEM_TOTAL>>>(x, didx, out);
}